// round 13
// baseline (speedup 1.0000x reference)
#include <cuda_runtime.h>
#include <cuda_fp16.h>
#include <mma.h>
#include <math.h>

using namespace nvcuda;

// Problem constants
constexpr int B_ = 8;
constexpr int T_ = 2048;
constexpr int C_ = 1024;
constexpr int M_ROWS = B_ * T_;      // 16384
constexpr int N_QKV  = 3 * C_;       // 3072
constexpr int NBLK   = T_ / 128;     // 16 col-blocks per row for partial sums

// GEMM tiling: 128x128 CTA tile, 4 warps (2Mx2N), warp tile 64x64, BK=32
constexpr int BM = 128;
constexpr int BN = 128;
constexpr int BK = 32;               // 32 halves = 64B per row
constexpr int AS_STRIDE = BK + 16;   // 48 halves
constexpr int BN_STRIDE = BN + 8;    // 136 halves
constexpr int A_BUF = BM * AS_STRIDE;   // 6144 halves (12KB)
constexpr int B_BUF = BM * AS_STRIDE;   // 6144 (>= 32*136=4352)
constexpr size_t SMEM_BYTES = 73728;    // GEMM (48KB) + epi staging (66KB)
constexpr int STG_LD = BN + 4;          // 132 floats, epi staging stride

// Scratch (device globals)
__device__ __half g_xh[(size_t)M_ROWS * C_];
__device__ __half g_wqh[(size_t)C_ * N_QKV];
__device__ __half g_wph[(size_t)C_ * C_];
__device__ __half g_qkv[(size_t)M_ROWS * N_QKV];   // [B*T, 3C]
__device__ __half g_S[(size_t)B_ * T_ * T_];       // E = exp(scores)
__device__ __half g_O[(size_t)M_ROWS * C_];
__device__ float  g_part[(size_t)M_ROWS * NBLK];
__device__ float  g_inv[(size_t)M_ROWS];

__device__ __forceinline__ unsigned smem_u32(const void* p) {
    return (unsigned)__cvta_generic_to_shared(p);
}
__device__ __forceinline__ void cp16(unsigned s, const void* g) {
    asm volatile("cp.async.cg.shared.global [%0], [%1], 16;\n" :: "r"(s), "l"(g));
}
__device__ __forceinline__ void cp_commit() {
    asm volatile("cp.async.commit_group;\n" ::: "memory");
}
template <int N>
__device__ __forceinline__ void cp_wait() {
    asm volatile("cp.async.wait_group %0;\n" :: "n"(N) : "memory");
}

// ---------------------------------------------------------------------------
// fp32 -> fp16 conversion, 8 elements per thread (16B stores)
// ---------------------------------------------------------------------------
__global__ void __launch_bounds__(256)
f2h_kernel(const float* __restrict__ in, __half* __restrict__ out, int n8)
{
    int i = blockIdx.x * blockDim.x + threadIdx.x;
    if (i >= n8) return;
    float4 a = ((const float4*)in)[2 * i];
    float4 b = ((const float4*)in)[2 * i + 1];
    __half2 h0 = __floats2half2_rn(a.x, a.y);
    __half2 h1 = __floats2half2_rn(a.z, a.w);
    __half2 h2 = __floats2half2_rn(b.x, b.y);
    __half2 h3 = __floats2half2_rn(b.z, b.w);
    uint4 u;
    u.x = *reinterpret_cast<unsigned*>(&h0);
    u.y = *reinterpret_cast<unsigned*>(&h1);
    u.z = *reinterpret_cast<unsigned*>(&h2);
    u.w = *reinterpret_cast<unsigned*>(&h3);
    ((uint4*)out)[i] = u;
}

// Deterministic row-sum inversion: inv[g] = 1 / sum_{bx<=i/128} part[g][bx]
__global__ void __launch_bounds__(256)
inv_rowsum_kernel(const float* __restrict__ part, float* __restrict__ inv)
{
    int g = blockIdx.x * blockDim.x + threadIdx.x;
    if (g >= M_ROWS) return;
    int i = g % T_;
    int nb = (i >> 7) + 1;
    float s = 0.0f;
    for (int b = 0; b < nb; b++) s += part[(size_t)g * NBLK + b];
    inv[g] = 1.0f / s;
}

// ---------------------------------------------------------------------------
// fp16 WMMA GEMM (fp32 accum), 128x128x32 tile, 128 threads (4 warps,
// warp tile 64x64, m16n16k16), cp.async double-buffered staging with all
// addresses hoisted out of the main loop.
// TRANS_B: B is [N,K] (A@B^T) else [K,N] (A@B).
// CAUSAL: 0 none; 1 skip blocks above diagonal; 2 K-limit to m0+BM.
// EPI: 0 fp32 store (final); 1 fp16 store; 2 exp+mask+rowsum-partials (fp16);
//      3 row-scale by aux[row] (fp16).
// ---------------------------------------------------------------------------
template <bool TRANS_B, int CAUSAL, int EPI>
__global__ void __launch_bounds__(128, 2)
gemm_fp16_kernel(const __half* __restrict__ Ag, const __half* __restrict__ Bg,
                 void* __restrict__ Cgv, float* __restrict__ aux,
                 int K, int lda, int ldb, int ldc,
                 long long sA, long long sB, long long sC, float alpha)
{
    extern __shared__ char smem_raw[];
    __half* As = (__half*)smem_raw;                // [2][A_BUF]
    __half* Bs = (__half*)smem_raw + 2 * A_BUF;    // [2][B_BUF]

    const long long bz = blockIdx.z;
    const __half* A  = Ag + bz * sA;
    const __half* Bp = Bg + bz * sB;

    const int m0 = blockIdx.y * BM;
    const int n0 = blockIdx.x * BN;

    if (CAUSAL == 1 && n0 > m0 + BM - 1) return;
    int kend = K;
    if (CAUSAL == 2) kend = min(K, m0 + BM);
    const int ntiles = kend / BK;

    const int tid  = threadIdx.x;
    const int warp = tid >> 5;
    const int lane = tid & 31;
    const int wm   = (warp >> 1) * 64;
    const int wn   = (warp & 1) * 64;

    wmma::fragment<wmma::accumulator, 16, 16, 16, float> acc[4][4];
    #pragma unroll
    for (int i = 0; i < 4; i++)
        #pragma unroll
        for (int j = 0; j < 4; j++)
            wmma::fill_fragment(acc[i][j], 0.0f);

    // ---- Hoisted staging addresses ----
    // A: 512 chunks/stage, 4 per thread: rows arow+32j, fixed 8-half col.
    const int arow = tid >> 2, acol = (tid & 3) * 8;
    const __half* Agsrc = &A[(size_t)(m0 + arow) * lda + acol];
    unsigned AsDst[2];
    AsDst[0] = smem_u32(&As[arow * AS_STRIDE + acol]);
    AsDst[1] = smem_u32(&As[A_BUF + arow * AS_STRIDE + acol]);

    const int brow = TRANS_B ? (tid >> 2) : (tid >> 4);
    const int bcol = TRANS_B ? ((tid & 3) * 8) : ((tid & 15) * 8);
    const __half* Bgsrc = TRANS_B
        ? &Bp[(size_t)(n0 + brow) * ldb + bcol]
        : &Bp[(size_t)brow * ldb + n0 + bcol];
    const int bsm_stride = TRANS_B ? AS_STRIDE : BN_STRIDE;
    unsigned BsDst[2];
    BsDst[0] = smem_u32(&Bs[brow * bsm_stride + bcol]);
    BsDst[1] = smem_u32(&Bs[B_BUF + brow * bsm_stride + bcol]);

    auto stage = [&](int kt, int b) {
        const int kbase = kt * BK;
        #pragma unroll
        for (int j = 0; j < 4; j++)
            cp16(AsDst[b] + j * 32 * AS_STRIDE * 2,
                 Agsrc + (size_t)j * 32 * lda + kbase);
        if constexpr (TRANS_B) {
            #pragma unroll
            for (int j = 0; j < 4; j++)
                cp16(BsDst[b] + j * 32 * AS_STRIDE * 2,
                     Bgsrc + (size_t)j * 32 * ldb + kbase);
        } else {
            #pragma unroll
            for (int j = 0; j < 4; j++)
                cp16(BsDst[b] + j * 8 * BN_STRIDE * 2,
                     Bgsrc + (size_t)(kbase + j * 8) * ldb);
        }
    };

    // ---- Hoisted per-warp fragment base pointers ----
    const __half* AfB[2] = { &As[wm * AS_STRIDE], &As[A_BUF + wm * AS_STRIDE] };
    const __half* BfB[2] = {
        TRANS_B ? &Bs[wn * AS_STRIDE] : &Bs[wn],
        TRANS_B ? &Bs[B_BUF + wn * AS_STRIDE] : &Bs[B_BUF + wn]
    };

    stage(0, 0);
    cp_commit();

    using FragA = wmma::fragment<wmma::matrix_a, 16, 16, 16, __half,
                                 wmma::row_major>;

    for (int kt = 0; kt < ntiles; kt++) {
        const int buf = kt & 1;
        if (kt + 1 < ntiles) {
            stage(kt + 1, (kt + 1) & 1);
            cp_commit();
            cp_wait<1>();
        } else {
            cp_wait<0>();
        }
        __syncthreads();

        const __half* Abase = AfB[buf];
        const __half* Bbase = BfB[buf];

        #pragma unroll
        for (int kk = 0; kk < BK; kk += 16) {
            FragA af[4];
            #pragma unroll
            for (int im = 0; im < 4; im++)
                wmma::load_matrix_sync(af[im],
                    Abase + im * 16 * AS_STRIDE + kk, AS_STRIDE);
            if constexpr (TRANS_B) {
                wmma::fragment<wmma::matrix_b, 16, 16, 16, __half,
                               wmma::col_major> bf[4];
                #pragma unroll
                for (int in = 0; in < 4; in++)
                    wmma::load_matrix_sync(bf[in],
                        Bbase + in * 16 * AS_STRIDE + kk, AS_STRIDE);
                #pragma unroll
                for (int im = 0; im < 4; im++)
                    #pragma unroll
                    for (int in = 0; in < 4; in++)
                        wmma::mma_sync(acc[im][in], af[im], bf[in], acc[im][in]);
            } else {
                wmma::fragment<wmma::matrix_b, 16, 16, 16, __half,
                               wmma::row_major> bf[4];
                #pragma unroll
                for (int in = 0; in < 4; in++)
                    wmma::load_matrix_sync(bf[in],
                        Bbase + kk * BN_STRIDE + in * 16, BN_STRIDE);
                #pragma unroll
                for (int im = 0; im < 4; im++)
                    #pragma unroll
                    for (int in = 0; in < 4; in++)
                        wmma::mma_sync(acc[im][in], af[im], bf[in], acc[im][in]);
            }
        }
        __syncthreads();
    }

    // ---- alpha scale ----
    #pragma unroll
    for (int im = 0; im < 4; im++)
        #pragma unroll
        for (int in = 0; in < 4; in++)
            #pragma unroll
            for (int t = 0; t < acc[im][in].num_elements; t++)
                acc[im][in].x[t] *= alpha;

    if constexpr (EPI == 0) {
        float* Cp = (float*)Cgv + bz * sC;
        #pragma unroll
        for (int im = 0; im < 4; im++)
            #pragma unroll
            for (int in = 0; in < 4; in++)
                wmma::store_matrix_sync(
                    &Cp[(size_t)(m0 + wm + im * 16) * ldc + n0 + wn + in * 16],
                    acc[im][in], ldc, wmma::mem_row_major);
    } else {
        __half* Cp = (__half*)Cgv + bz * sC;
        // Stage full 128x128 fp32 tile in smem, then half2 sweep.
        float* stg = (float*)smem_raw;   // 128 x 132 floats = 67584 B
        #pragma unroll
        for (int im = 0; im < 4; im++)
            #pragma unroll
            for (int in = 0; in < 4; in++)
                wmma::store_matrix_sync(
                    &stg[(wm + im * 16) * STG_LD + wn + in * 16],
                    acc[im][in], STG_LD, wmma::mem_row_major);
        __syncthreads();

        const int r0 = warp * 32;
        #pragma unroll 2
        for (int rr = 0; rr < 32; rr++) {
            const int r  = r0 + rr;
            const int gi = m0 + r;              // in-batch row (m0 < T)
            if constexpr (EPI == 2) {
                float s = 0.0f;
                #pragma unroll
                for (int cb = 0; cb < 2; cb++) {
                    const int c  = cb * 64 + lane * 2;
                    const int j0 = n0 + c;
                    float v0 = stg[r * STG_LD + c];
                    float v1 = stg[r * STG_LD + c + 1];
                    float e0 = (j0     <= gi) ? __expf(v0) : 0.0f;
                    float e1 = (j0 + 1 <= gi) ? __expf(v1) : 0.0f;
                    __half2 h = __floats2half2_rn(e0, e1);
                    s += __low2float(h) + __high2float(h);
                    *(__half2*)&Cp[(size_t)gi * ldc + j0] = h;
                }
                #pragma unroll
                for (int o = 16; o; o >>= 1)
                    s += __shfl_xor_sync(0xFFFFFFFFu, s, o);
                if (lane == 0)
                    aux[(bz * T_ + gi) * NBLK + blockIdx.x] = s;
            } else if constexpr (EPI == 3) {
                float sc = aux[bz * T_ + gi];
                #pragma unroll
                for (int cb = 0; cb < 2; cb++) {
                    const int c = cb * 64 + lane * 2;
                    float v0 = stg[r * STG_LD + c] * sc;
                    float v1 = stg[r * STG_LD + c + 1] * sc;
                    *(__half2*)&Cp[(size_t)gi * ldc + n0 + c] =
                        __floats2half2_rn(v0, v1);
                }
            } else {  // EPI == 1: plain fp16 store
                #pragma unroll
                for (int cb = 0; cb < 2; cb++) {
                    const int c = cb * 64 + lane * 2;
                    float v0 = stg[r * STG_LD + c];
                    float v1 = stg[r * STG_LD + c + 1];
                    *(__half2*)&Cp[(size_t)gi * ldc + n0 + c] =
                        __floats2half2_rn(v0, v1);
                }
            }
        }
    }
}

// ---------------------------------------------------------------------------
// Launch
// ---------------------------------------------------------------------------
extern "C" void kernel_launch(void* const* d_in, const int* in_sizes, int n_in,
                              void* d_out, int out_size)
{
    const float* x     = (const float*)d_in[0];   // [B, T, C]
    const float* Wqkv  = (const float*)d_in[1];   // [C, 3C]
    const float* Wproj = (const float*)d_in[2];   // [C, C]
    float* out = (float*)d_out;                   // [B, T, C]

    static __half *xh = nullptr, *wqh = nullptr, *wph = nullptr;
    static __half *qkv = nullptr, *S = nullptr, *O = nullptr;
    static float *part = nullptr, *inv = nullptr;
    if (!qkv) {
        cudaGetSymbolAddress((void**)&xh,   g_xh);
        cudaGetSymbolAddress((void**)&wqh,  g_wqh);
        cudaGetSymbolAddress((void**)&wph,  g_wph);
        cudaGetSymbolAddress((void**)&qkv,  g_qkv);
        cudaGetSymbolAddress((void**)&S,    g_S);
        cudaGetSymbolAddress((void**)&O,    g_O);
        cudaGetSymbolAddress((void**)&part, g_part);
        cudaGetSymbolAddress((void**)&inv,  g_inv);
        cudaFuncSetAttribute(gemm_fp16_kernel<false, 0, 1>,
            cudaFuncAttributeMaxDynamicSharedMemorySize, (int)SMEM_BYTES);
        cudaFuncSetAttribute(gemm_fp16_kernel<true, 1, 2>,
            cudaFuncAttributeMaxDynamicSharedMemorySize, (int)SMEM_BYTES);
        cudaFuncSetAttribute(gemm_fp16_kernel<false, 2, 3>,
            cudaFuncAttributeMaxDynamicSharedMemorySize, (int)SMEM_BYTES);
        cudaFuncSetAttribute(gemm_fp16_kernel<false, 0, 0>,
            cudaFuncAttributeMaxDynamicSharedMemorySize, (int)SMEM_BYTES);
    }

    const float scale = 1.0f / 32.0f;   // C^-0.5
    dim3 blk(128);

    // 0. convert inputs to fp16
    f2h_kernel<<<(M_ROWS * C_ / 8 + 255) / 256, 256>>>(x, xh, M_ROWS * C_ / 8);
    f2h_kernel<<<(C_ * N_QKV / 8 + 255) / 256, 256>>>(Wqkv, wqh, C_ * N_QKV / 8);
    f2h_kernel<<<(C_ * C_ / 8 + 255) / 256, 256>>>(Wproj, wph, C_ * C_ / 8);

    // 1. qkv = x @ Wqkv (fp16 out)
    gemm_fp16_kernel<false, 0, 1>
        <<<dim3(N_QKV / BN, M_ROWS / BM, 1), blk, SMEM_BYTES>>>(
        xh, wqh, qkv, nullptr, C_, C_, N_QKV, N_QKV, 0, 0, 0, 1.0f);

    // 2. E_b = exp(scale * Q_b @ K_b^T) causal-masked; partial row sums.
    gemm_fp16_kernel<true, 1, 2>
        <<<dim3(T_ / BN, T_ / BM, B_), blk, SMEM_BYTES>>>(
        qkv, qkv + C_, S, part, C_, N_QKV, N_QKV, T_,
        (long long)T_ * N_QKV, (long long)T_ * N_QKV, (long long)T_ * T_,
        scale);

    // 3. inv[row] = 1 / rowsum
    inv_rowsum_kernel<<<(M_ROWS + 255) / 256, 256>>>(part, inv);

    // 4. O_b = diag(inv) * E_b @ V_b (K-limited; fp16 out)
    gemm_fp16_kernel<false, 2, 3>
        <<<dim3(C_ / BN, T_ / BM, B_), blk, SMEM_BYTES>>>(
        S, qkv + 2 * C_, O, inv, T_, T_, N_QKV, C_,
        (long long)T_ * T_, (long long)T_ * N_QKV, (long long)T_ * C_,
        1.0f);

    // 5. out = O @ Wproj (fp32 final)
    gemm_fp16_kernel<false, 0, 0>
        <<<dim3(C_ / BN, M_ROWS / BM, 1), blk, SMEM_BYTES>>>(
        O, wph, out, nullptr, C_, C_, C_, C_, 0, 0, 0, 1.0f);
}

// round 14
// speedup vs baseline: 1.3824x; 1.3824x over previous
#include <cuda_runtime.h>
#include <cuda_fp16.h>
#include <mma.h>
#include <math.h>

using namespace nvcuda;

// Problem constants
constexpr int B_ = 8;
constexpr int T_ = 2048;
constexpr int C_ = 1024;
constexpr int M_ROWS = B_ * T_;      // 16384
constexpr int N_QKV  = 3 * C_;       // 3072
constexpr int NBLK   = T_ / 128;     // 16 col-blocks per row for partial sums

// GEMM tiling: 128x128 CTA tile, 4 warps (2Mx2N), warp tile 64x64, BK=32
constexpr int BM = 128;
constexpr int BN = 128;
constexpr int BK = 32;               // 32 halves = 64B per row
constexpr int AS_STRIDE = BK + 16;   // 48 halves
constexpr int BN_STRIDE = BN + 8;    // 136 halves
constexpr int A_BUF = BM * AS_STRIDE;   // 6144 halves (12KB)
constexpr int B_BUF = BM * AS_STRIDE;   // 6144 (>= 32*136=4352)
constexpr size_t SMEM_BYTES = 73728;    // GEMM (48KB) + epi staging (66KB)
constexpr int STG_LD = BN + 4;          // 132 floats, epi staging stride

// Scratch (device globals)
__device__ __half g_xh[(size_t)M_ROWS * C_];
__device__ __half g_wqh[(size_t)C_ * N_QKV];
__device__ __half g_wph[(size_t)C_ * C_];
__device__ __half g_qkv[(size_t)M_ROWS * N_QKV];   // [B*T, 3C]
__device__ __half g_S[(size_t)B_ * T_ * T_];       // E = exp(scores)
__device__ __half g_O[(size_t)M_ROWS * C_];
__device__ float  g_part[(size_t)M_ROWS * NBLK];
__device__ float  g_inv[(size_t)M_ROWS];

__device__ __forceinline__ unsigned smem_u32(const void* p) {
    return (unsigned)__cvta_generic_to_shared(p);
}
__device__ __forceinline__ void cp16(unsigned s, const void* g) {
    asm volatile("cp.async.cg.shared.global [%0], [%1], 16;\n" :: "r"(s), "l"(g));
}
__device__ __forceinline__ void cp_commit() {
    asm volatile("cp.async.commit_group;\n" ::: "memory");
}
template <int N>
__device__ __forceinline__ void cp_wait() {
    asm volatile("cp.async.wait_group %0;\n" :: "n"(N) : "memory");
}

// ---------------------------------------------------------------------------
// fp32 -> fp16 conversion, 8 elements per thread (16B stores)
// ---------------------------------------------------------------------------
__global__ void __launch_bounds__(256)
f2h_kernel(const float* __restrict__ in, __half* __restrict__ out, int n8)
{
    int i = blockIdx.x * blockDim.x + threadIdx.x;
    if (i >= n8) return;
    float4 a = ((const float4*)in)[2 * i];
    float4 b = ((const float4*)in)[2 * i + 1];
    __half2 h0 = __floats2half2_rn(a.x, a.y);
    __half2 h1 = __floats2half2_rn(a.z, a.w);
    __half2 h2 = __floats2half2_rn(b.x, b.y);
    __half2 h3 = __floats2half2_rn(b.z, b.w);
    uint4 u;
    u.x = *reinterpret_cast<unsigned*>(&h0);
    u.y = *reinterpret_cast<unsigned*>(&h1);
    u.z = *reinterpret_cast<unsigned*>(&h2);
    u.w = *reinterpret_cast<unsigned*>(&h3);
    ((uint4*)out)[i] = u;
}

// Deterministic row-sum inversion: inv[g] = 1 / sum_{bx<=i/128} part[g][bx]
__global__ void __launch_bounds__(256)
inv_rowsum_kernel(const float* __restrict__ part, float* __restrict__ inv)
{
    int g = blockIdx.x * blockDim.x + threadIdx.x;
    if (g >= M_ROWS) return;
    int i = g % T_;
    int nb = (i >> 7) + 1;
    float s = 0.0f;
    for (int b = 0; b < nb; b++) s += part[(size_t)g * NBLK + b];
    inv[g] = 1.0f / s;
}

// ---------------------------------------------------------------------------
// fp16 WMMA GEMM (fp32 accum), 128x128x32 tile, 128 threads (4 warps,
// warp tile 64x64, m16n16k16), cp.async double-buffered staging.
// (R10 core, verbatim — do not touch the main loop.)
// TRANS_B: B is [N,K] (A@B^T) else [K,N] (A@B).
// CAUSAL: 0 none; 1 skip blocks above diagonal; 2 K-limit to m0+BM.
// EPI: 0 fp32 store (final); 1 fp16 store DIRECT from fragments;
//      2 exp+mask+rowsum-partials (fp16); 3 row-scale by aux[row] (fp16).
// ---------------------------------------------------------------------------
template <bool TRANS_B, int CAUSAL, int EPI>
__global__ void __launch_bounds__(128, 2)
gemm_fp16_kernel(const __half* __restrict__ Ag, const __half* __restrict__ Bg,
                 void* __restrict__ Cgv, float* __restrict__ aux,
                 int K, int lda, int ldb, int ldc,
                 long long sA, long long sB, long long sC, float alpha)
{
    extern __shared__ char smem_raw[];
    __half* As = (__half*)smem_raw;                // [2][A_BUF]
    __half* Bs = (__half*)smem_raw + 2 * A_BUF;    // [2][B_BUF]

    const long long bz = blockIdx.z;
    const __half* A  = Ag + bz * sA;
    const __half* Bp = Bg + bz * sB;

    const int m0 = blockIdx.y * BM;
    const int n0 = blockIdx.x * BN;

    if (CAUSAL == 1 && n0 > m0 + BM - 1) return;
    int kend = K;
    if (CAUSAL == 2) kend = min(K, m0 + BM);
    const int ntiles = kend / BK;

    const int tid  = threadIdx.x;
    const int warp = tid >> 5;
    const int lane = tid & 31;
    const int wm   = (warp >> 1) * 64;
    const int wn   = (warp & 1) * 64;

    wmma::fragment<wmma::accumulator, 16, 16, 16, float> acc[4][4];
    #pragma unroll
    for (int i = 0; i < 4; i++)
        #pragma unroll
        for (int j = 0; j < 4; j++)
            wmma::fill_fragment(acc[i][j], 0.0f);

    auto stage = [&](int kt, int b) {
        const int kbase = kt * BK;
        // A tile 128x32 halves: 512 16B-chunks (8 halves each), 4/thread
        #pragma unroll
        for (int i = tid; i < (BM * BK) / 8; i += 128) {
            int r = i >> 2, c = (i & 3) * 8;
            cp16(smem_u32(&As[b * A_BUF + r * AS_STRIDE + c]),
                 &A[(size_t)(m0 + r) * lda + kbase + c]);
        }
        if constexpr (TRANS_B) {
            #pragma unroll
            for (int i = tid; i < (BN * BK) / 8; i += 128) {
                int r = i >> 2, c = (i & 3) * 8;
                cp16(smem_u32(&Bs[b * B_BUF + r * AS_STRIDE + c]),
                     &Bp[(size_t)(n0 + r) * ldb + kbase + c]);
            }
        } else {
            // B tile 32x128 halves: 512 chunks
            #pragma unroll
            for (int i = tid; i < (BK * BN) / 8; i += 128) {
                int r = i >> 4, c = (i & 15) * 8;
                cp16(smem_u32(&Bs[b * B_BUF + r * BN_STRIDE + c]),
                     &Bp[(size_t)(kbase + r) * ldb + n0 + c]);
            }
        }
    };

    stage(0, 0);
    cp_commit();

    using FragA = wmma::fragment<wmma::matrix_a, 16, 16, 16, __half,
                                 wmma::row_major>;

    for (int kt = 0; kt < ntiles; kt++) {
        const int buf = kt & 1;
        if (kt + 1 < ntiles) {
            stage(kt + 1, (kt + 1) & 1);
            cp_commit();
            cp_wait<1>();
        } else {
            cp_wait<0>();
        }
        __syncthreads();

        const __half* Abase = &As[buf * A_BUF];
        const __half* Bbase = &Bs[buf * B_BUF];

        #pragma unroll
        for (int kk = 0; kk < BK; kk += 16) {
            FragA af[4];
            #pragma unroll
            for (int im = 0; im < 4; im++)
                wmma::load_matrix_sync(af[im],
                    &Abase[(wm + im * 16) * AS_STRIDE + kk], AS_STRIDE);
            if constexpr (TRANS_B) {
                wmma::fragment<wmma::matrix_b, 16, 16, 16, __half,
                               wmma::col_major> bf[4];
                #pragma unroll
                for (int in = 0; in < 4; in++)
                    wmma::load_matrix_sync(bf[in],
                        &Bbase[(wn + in * 16) * AS_STRIDE + kk], AS_STRIDE);
                #pragma unroll
                for (int im = 0; im < 4; im++)
                    #pragma unroll
                    for (int in = 0; in < 4; in++)
                        wmma::mma_sync(acc[im][in], af[im], bf[in], acc[im][in]);
            } else {
                wmma::fragment<wmma::matrix_b, 16, 16, 16, __half,
                               wmma::row_major> bf[4];
                #pragma unroll
                for (int in = 0; in < 4; in++)
                    wmma::load_matrix_sync(bf[in],
                        &Bbase[kk * BN_STRIDE + wn + in * 16], BN_STRIDE);
                #pragma unroll
                for (int im = 0; im < 4; im++)
                    #pragma unroll
                    for (int in = 0; in < 4; in++)
                        wmma::mma_sync(acc[im][in], af[im], bf[in], acc[im][in]);
            }
        }
        __syncthreads();
    }

    // ---- alpha scale ----
    #pragma unroll
    for (int im = 0; im < 4; im++)
        #pragma unroll
        for (int in = 0; in < 4; in++)
            #pragma unroll
            for (int t = 0; t < acc[im][in].num_elements; t++)
                acc[im][in].x[t] *= alpha;

    if constexpr (EPI == 0) {
        float* Cp = (float*)Cgv + bz * sC;
        #pragma unroll
        for (int im = 0; im < 4; im++)
            #pragma unroll
            for (int in = 0; in < 4; in++)
                wmma::store_matrix_sync(
                    &Cp[(size_t)(m0 + wm + im * 16) * ldc + n0 + wn + in * 16],
                    acc[im][in], ldc, wmma::mem_row_major);
    } else if constexpr (EPI == 1) {
        // Direct fragment->fp16 conversion and store (no smem staging).
        // Element-wise copy between same-shape accumulator fragments is the
        // sanctioned idiom (cudaTensorCoreGemm sample).
        __half* Cp = (__half*)Cgv + bz * sC;
        #pragma unroll
        for (int im = 0; im < 4; im++)
            #pragma unroll
            for (int in = 0; in < 4; in++) {
                wmma::fragment<wmma::accumulator, 16, 16, 16, __half> hacc;
                #pragma unroll
                for (int t = 0; t < hacc.num_elements; t++)
                    hacc.x[t] = __float2half(acc[im][in].x[t]);
                wmma::store_matrix_sync(
                    &Cp[(size_t)(m0 + wm + im * 16) * ldc + n0 + wn + in * 16],
                    hacc, ldc, wmma::mem_row_major);
            }
    } else {
        __half* Cp = (__half*)Cgv + bz * sC;
        // Stage full 128x128 fp32 tile in smem, then half2 sweep.
        float* stg = (float*)smem_raw;   // 128 x 132 floats = 67584 B
        #pragma unroll
        for (int im = 0; im < 4; im++)
            #pragma unroll
            for (int in = 0; in < 4; in++)
                wmma::store_matrix_sync(
                    &stg[(wm + im * 16) * STG_LD + wn + in * 16],
                    acc[im][in], STG_LD, wmma::mem_row_major);
        __syncthreads();

        const int r0 = warp * 32;
        #pragma unroll 2
        for (int rr = 0; rr < 32; rr++) {
            const int r  = r0 + rr;
            const int gi = m0 + r;              // in-batch row (m0 < T)
            if constexpr (EPI == 2) {
                float s = 0.0f;
                #pragma unroll
                for (int cb = 0; cb < 2; cb++) {
                    const int c  = cb * 64 + lane * 2;
                    const int j0 = n0 + c;
                    float v0 = stg[r * STG_LD + c];
                    float v1 = stg[r * STG_LD + c + 1];
                    float e0 = (j0     <= gi) ? __expf(v0) : 0.0f;
                    float e1 = (j0 + 1 <= gi) ? __expf(v1) : 0.0f;
                    __half2 h = __floats2half2_rn(e0, e1);
                    s += __low2float(h) + __high2float(h);
                    *(__half2*)&Cp[(size_t)gi * ldc + j0] = h;
                }
                #pragma unroll
                for (int o = 16; o; o >>= 1)
                    s += __shfl_xor_sync(0xFFFFFFFFu, s, o);
                if (lane == 0)
                    aux[(bz * T_ + gi) * NBLK + blockIdx.x] = s;
            } else {  // EPI == 3: row scale
                float sc = aux[bz * T_ + gi];
                #pragma unroll
                for (int cb = 0; cb < 2; cb++) {
                    const int c = cb * 64 + lane * 2;
                    float v0 = stg[r * STG_LD + c] * sc;
                    float v1 = stg[r * STG_LD + c + 1] * sc;
                    *(__half2*)&Cp[(size_t)gi * ldc + n0 + c] =
                        __floats2half2_rn(v0, v1);
                }
            }
        }
    }
}

// ---------------------------------------------------------------------------
// Launch
// ---------------------------------------------------------------------------
extern "C" void kernel_launch(void* const* d_in, const int* in_sizes, int n_in,
                              void* d_out, int out_size)
{
    const float* x     = (const float*)d_in[0];   // [B, T, C]
    const float* Wqkv  = (const float*)d_in[1];   // [C, 3C]
    const float* Wproj = (const float*)d_in[2];   // [C, C]
    float* out = (float*)d_out;                   // [B, T, C]

    static __half *xh = nullptr, *wqh = nullptr, *wph = nullptr;
    static __half *qkv = nullptr, *S = nullptr, *O = nullptr;
    static float *part = nullptr, *inv = nullptr;
    if (!qkv) {
        cudaGetSymbolAddress((void**)&xh,   g_xh);
        cudaGetSymbolAddress((void**)&wqh,  g_wqh);
        cudaGetSymbolAddress((void**)&wph,  g_wph);
        cudaGetSymbolAddress((void**)&qkv,  g_qkv);
        cudaGetSymbolAddress((void**)&S,    g_S);
        cudaGetSymbolAddress((void**)&O,    g_O);
        cudaGetSymbolAddress((void**)&part, g_part);
        cudaGetSymbolAddress((void**)&inv,  g_inv);
        cudaFuncSetAttribute(gemm_fp16_kernel<false, 0, 1>,
            cudaFuncAttributeMaxDynamicSharedMemorySize, (int)SMEM_BYTES);
        cudaFuncSetAttribute(gemm_fp16_kernel<true, 1, 2>,
            cudaFuncAttributeMaxDynamicSharedMemorySize, (int)SMEM_BYTES);
        cudaFuncSetAttribute(gemm_fp16_kernel<false, 2, 3>,
            cudaFuncAttributeMaxDynamicSharedMemorySize, (int)SMEM_BYTES);
        cudaFuncSetAttribute(gemm_fp16_kernel<false, 0, 0>,
            cudaFuncAttributeMaxDynamicSharedMemorySize, (int)SMEM_BYTES);
    }

    const float scale = 1.0f / 32.0f;   // C^-0.5
    dim3 blk(128);

    // 0. convert inputs to fp16
    f2h_kernel<<<(M_ROWS * C_ / 8 + 255) / 256, 256>>>(x, xh, M_ROWS * C_ / 8);
    f2h_kernel<<<(C_ * N_QKV / 8 + 255) / 256, 256>>>(Wqkv, wqh, C_ * N_QKV / 8);
    f2h_kernel<<<(C_ * C_ / 8 + 255) / 256, 256>>>(Wproj, wph, C_ * C_ / 8);

    // 1. qkv = x @ Wqkv (fp16 out, direct fragment store)
    gemm_fp16_kernel<false, 0, 1>
        <<<dim3(N_QKV / BN, M_ROWS / BM, 1), blk, SMEM_BYTES>>>(
        xh, wqh, qkv, nullptr, C_, C_, N_QKV, N_QKV, 0, 0, 0, 1.0f);

    // 2. E_b = exp(scale * Q_b @ K_b^T) causal-masked; partial row sums.
    gemm_fp16_kernel<true, 1, 2>
        <<<dim3(T_ / BN, T_ / BM, B_), blk, SMEM_BYTES>>>(
        qkv, qkv + C_, S, part, C_, N_QKV, N_QKV, T_,
        (long long)T_ * N_QKV, (long long)T_ * N_QKV, (long long)T_ * T_,
        scale);

    // 3. inv[row] = 1 / rowsum
    inv_rowsum_kernel<<<(M_ROWS + 255) / 256, 256>>>(part, inv);

    // 4. O_b = diag(inv) * E_b @ V_b (K-limited; fp16 out)
    gemm_fp16_kernel<false, 2, 3>
        <<<dim3(C_ / BN, T_ / BM, B_), blk, SMEM_BYTES>>>(
        S, qkv + 2 * C_, O, inv, T_, T_, N_QKV, C_,
        (long long)T_ * T_, (long long)T_ * N_QKV, (long long)T_ * C_,
        1.0f);

    // 5. out = O @ Wproj (fp32 final)
    gemm_fp16_kernel<false, 0, 0>
        <<<dim3(C_ / BN, M_ROWS / BM, 1), blk, SMEM_BYTES>>>(
        O, wph, out, nullptr, C_, C_, C_, C_, 0, 0, 0, 1.0f);
}

// round 15
// speedup vs baseline: 1.3882x; 1.0042x over previous
#include <cuda_runtime.h>
#include <cuda_fp16.h>
#include <mma.h>
#include <math.h>

using namespace nvcuda;

// Problem constants
constexpr int B_ = 8;
constexpr int T_ = 2048;
constexpr int C_ = 1024;
constexpr int M_ROWS = B_ * T_;      // 16384
constexpr int N_QKV  = 3 * C_;       // 3072
constexpr int NBLK   = T_ / 128;     // 16 col-blocks per row for partial sums

// GEMM tiling: 128x128 CTA tile, 4 warps (2Mx2N), warp tile 64x64, BK=32
constexpr int BM = 128;
constexpr int BN = 128;
constexpr int BK = 32;               // 32 halves = 64B per row
constexpr int AS_STRIDE = BK + 16;   // 48 halves
constexpr int BN_STRIDE = BN + 8;    // 136 halves
constexpr int A_BUF = BM * AS_STRIDE;   // 6144 halves (12KB)
constexpr int B_BUF = BM * AS_STRIDE;   // 6144 (>= 32*136=4352)
constexpr size_t SMEM_BYTES = 73728;    // GEMM (48KB) + epi staging (66KB)
constexpr int STG_LD = BN + 4;          // 132 floats, epi staging stride

// Scratch (device globals)
__device__ __half g_xh[(size_t)M_ROWS * C_];
__device__ __half g_wqh[(size_t)C_ * N_QKV];
__device__ __half g_wph[(size_t)C_ * C_];
__device__ __half g_qkv[(size_t)M_ROWS * N_QKV];   // [B*T, 3C]
__device__ __half g_S[(size_t)B_ * T_ * T_];       // E = exp(scores)
__device__ __half g_O[(size_t)M_ROWS * C_];
__device__ float  g_part[(size_t)M_ROWS * NBLK];
__device__ float  g_inv[(size_t)M_ROWS];

__device__ __forceinline__ unsigned smem_u32(const void* p) {
    return (unsigned)__cvta_generic_to_shared(p);
}
__device__ __forceinline__ void cp16(unsigned s, const void* g) {
    asm volatile("cp.async.cg.shared.global [%0], [%1], 16;\n" :: "r"(s), "l"(g));
}
__device__ __forceinline__ void cp_commit() {
    asm volatile("cp.async.commit_group;\n" ::: "memory");
}
template <int N>
__device__ __forceinline__ void cp_wait() {
    asm volatile("cp.async.wait_group %0;\n" :: "n"(N) : "memory");
}

// ---------------------------------------------------------------------------
// fp32 -> fp16 conversion, 8 elements per thread (16B stores)
// ---------------------------------------------------------------------------
__global__ void __launch_bounds__(256)
f2h_kernel(const float* __restrict__ in, __half* __restrict__ out, int n8)
{
    int i = blockIdx.x * blockDim.x + threadIdx.x;
    if (i >= n8) return;
    float4 a = ((const float4*)in)[2 * i];
    float4 b = ((const float4*)in)[2 * i + 1];
    __half2 h0 = __floats2half2_rn(a.x, a.y);
    __half2 h1 = __floats2half2_rn(a.z, a.w);
    __half2 h2 = __floats2half2_rn(b.x, b.y);
    __half2 h3 = __floats2half2_rn(b.z, b.w);
    uint4 u;
    u.x = *reinterpret_cast<unsigned*>(&h0);
    u.y = *reinterpret_cast<unsigned*>(&h1);
    u.z = *reinterpret_cast<unsigned*>(&h2);
    u.w = *reinterpret_cast<unsigned*>(&h3);
    ((uint4*)out)[i] = u;
}

// Deterministic row-sum inversion: inv[g] = 1 / sum_{bx<=i/128} part[g][bx]
__global__ void __launch_bounds__(256)
inv_rowsum_kernel(const float* __restrict__ part, float* __restrict__ inv)
{
    int g = blockIdx.x * blockDim.x + threadIdx.x;
    if (g >= M_ROWS) return;
    int i = g % T_;
    int nb = (i >> 7) + 1;
    float s = 0.0f;
    for (int b = 0; b < nb; b++) s += part[(size_t)g * NBLK + b];
    inv[g] = 1.0f / s;
}

// ---------------------------------------------------------------------------
// fp16 WMMA GEMM (fp32 accum), 128x128x32 tile, 128 threads (4 warps,
// warp tile 64x64, m16n16k16), cp.async double-buffered staging.
// (R10 core, verbatim — do not touch the main loop.)
// TRANS_B: B is [N,K] (A@B^T) else [K,N] (A@B).
// CAUSAL: 0 none; 1 skip blocks above diagonal; 2 K-limit to m0+BM.
// EPI: 0 fp32 store (final); 1 fp16 store DIRECT from fragments;
//      2 exp+mask+rowsum-partials (fp16); 3 row-scale by aux[row] (fp16).
// ---------------------------------------------------------------------------
template <bool TRANS_B, int CAUSAL, int EPI>
__global__ void __launch_bounds__(128, 2)
gemm_fp16_kernel(const __half* __restrict__ Ag, const __half* __restrict__ Bg,
                 void* __restrict__ Cgv, float* __restrict__ aux,
                 int K, int lda, int ldb, int ldc,
                 long long sA, long long sB, long long sC, float alpha)
{
    extern __shared__ char smem_raw[];
    __half* As = (__half*)smem_raw;                // [2][A_BUF]
    __half* Bs = (__half*)smem_raw + 2 * A_BUF;    // [2][B_BUF]

    const long long bz = blockIdx.z;
    const __half* A  = Ag + bz * sA;
    const __half* Bp = Bg + bz * sB;

    const int m0 = blockIdx.y * BM;
    const int n0 = blockIdx.x * BN;

    if (CAUSAL == 1 && n0 > m0 + BM - 1) return;
    int kend = K;
    if (CAUSAL == 2) kend = min(K, m0 + BM);
    const int ntiles = kend / BK;

    const int tid  = threadIdx.x;
    const int warp = tid >> 5;
    const int lane = tid & 31;
    const int wm   = (warp >> 1) * 64;
    const int wn   = (warp & 1) * 64;

    wmma::fragment<wmma::accumulator, 16, 16, 16, float> acc[4][4];
    #pragma unroll
    for (int i = 0; i < 4; i++)
        #pragma unroll
        for (int j = 0; j < 4; j++)
            wmma::fill_fragment(acc[i][j], 0.0f);

    auto stage = [&](int kt, int b) {
        const int kbase = kt * BK;
        // A tile 128x32 halves: 512 16B-chunks (8 halves each), 4/thread
        #pragma unroll
        for (int i = tid; i < (BM * BK) / 8; i += 128) {
            int r = i >> 2, c = (i & 3) * 8;
            cp16(smem_u32(&As[b * A_BUF + r * AS_STRIDE + c]),
                 &A[(size_t)(m0 + r) * lda + kbase + c]);
        }
        if constexpr (TRANS_B) {
            #pragma unroll
            for (int i = tid; i < (BN * BK) / 8; i += 128) {
                int r = i >> 2, c = (i & 3) * 8;
                cp16(smem_u32(&Bs[b * B_BUF + r * AS_STRIDE + c]),
                     &Bp[(size_t)(n0 + r) * ldb + kbase + c]);
            }
        } else {
            // B tile 32x128 halves: 512 chunks
            #pragma unroll
            for (int i = tid; i < (BK * BN) / 8; i += 128) {
                int r = i >> 4, c = (i & 15) * 8;
                cp16(smem_u32(&Bs[b * B_BUF + r * BN_STRIDE + c]),
                     &Bp[(size_t)(kbase + r) * ldb + n0 + c]);
            }
        }
    };

    stage(0, 0);
    cp_commit();

    using FragA = wmma::fragment<wmma::matrix_a, 16, 16, 16, __half,
                                 wmma::row_major>;

    for (int kt = 0; kt < ntiles; kt++) {
        const int buf = kt & 1;
        if (kt + 1 < ntiles) {
            stage(kt + 1, (kt + 1) & 1);
            cp_commit();
            cp_wait<1>();
        } else {
            cp_wait<0>();
        }
        __syncthreads();

        const __half* Abase = &As[buf * A_BUF];
        const __half* Bbase = &Bs[buf * B_BUF];

        #pragma unroll
        for (int kk = 0; kk < BK; kk += 16) {
            FragA af[4];
            #pragma unroll
            for (int im = 0; im < 4; im++)
                wmma::load_matrix_sync(af[im],
                    &Abase[(wm + im * 16) * AS_STRIDE + kk], AS_STRIDE);
            if constexpr (TRANS_B) {
                wmma::fragment<wmma::matrix_b, 16, 16, 16, __half,
                               wmma::col_major> bf[4];
                #pragma unroll
                for (int in = 0; in < 4; in++)
                    wmma::load_matrix_sync(bf[in],
                        &Bbase[(wn + in * 16) * AS_STRIDE + kk], AS_STRIDE);
                #pragma unroll
                for (int im = 0; im < 4; im++)
                    #pragma unroll
                    for (int in = 0; in < 4; in++)
                        wmma::mma_sync(acc[im][in], af[im], bf[in], acc[im][in]);
            } else {
                wmma::fragment<wmma::matrix_b, 16, 16, 16, __half,
                               wmma::row_major> bf[4];
                #pragma unroll
                for (int in = 0; in < 4; in++)
                    wmma::load_matrix_sync(bf[in],
                        &Bbase[kk * BN_STRIDE + wn + in * 16], BN_STRIDE);
                #pragma unroll
                for (int im = 0; im < 4; im++)
                    #pragma unroll
                    for (int in = 0; in < 4; in++)
                        wmma::mma_sync(acc[im][in], af[im], bf[in], acc[im][in]);
            }
        }
        __syncthreads();
    }

    // ---- alpha scale ----
    #pragma unroll
    for (int im = 0; im < 4; im++)
        #pragma unroll
        for (int in = 0; in < 4; in++)
            #pragma unroll
            for (int t = 0; t < acc[im][in].num_elements; t++)
                acc[im][in].x[t] *= alpha;

    if constexpr (EPI == 0) {
        float* Cp = (float*)Cgv + bz * sC;
        #pragma unroll
        for (int im = 0; im < 4; im++)
            #pragma unroll
            for (int in = 0; in < 4; in++)
                wmma::store_matrix_sync(
                    &Cp[(size_t)(m0 + wm + im * 16) * ldc + n0 + wn + in * 16],
                    acc[im][in], ldc, wmma::mem_row_major);
    } else if constexpr (EPI == 1) {
        // Direct fragment->fp16 conversion and store (no smem staging).
        // Element-wise copy between same-shape accumulator fragments is the
        // sanctioned idiom (cudaTensorCoreGemm sample).
        __half* Cp = (__half*)Cgv + bz * sC;
        #pragma unroll
        for (int im = 0; im < 4; im++)
            #pragma unroll
            for (int in = 0; in < 4; in++) {
                wmma::fragment<wmma::accumulator, 16, 16, 16, __half> hacc;
                #pragma unroll
                for (int t = 0; t < hacc.num_elements; t++)
                    hacc.x[t] = __float2half(acc[im][in].x[t]);
                wmma::store_matrix_sync(
                    &Cp[(size_t)(m0 + wm + im * 16) * ldc + n0 + wn + in * 16],
                    hacc, ldc, wmma::mem_row_major);
            }
    } else {
        __half* Cp = (__half*)Cgv + bz * sC;
        // Stage full 128x128 fp32 tile in smem, then half2 sweep.
        float* stg = (float*)smem_raw;   // 128 x 132 floats = 67584 B
        #pragma unroll
        for (int im = 0; im < 4; im++)
            #pragma unroll
            for (int in = 0; in < 4; in++)
                wmma::store_matrix_sync(
                    &stg[(wm + im * 16) * STG_LD + wn + in * 16],
                    acc[im][in], STG_LD, wmma::mem_row_major);
        __syncthreads();

        const int r0 = warp * 32;
        #pragma unroll 2
        for (int rr = 0; rr < 32; rr++) {
            const int r  = r0 + rr;
            const int gi = m0 + r;              // in-batch row (m0 < T)
            if constexpr (EPI == 2) {
                float s = 0.0f;
                #pragma unroll
                for (int cb = 0; cb < 2; cb++) {
                    const int c  = cb * 64 + lane * 2;
                    const int j0 = n0 + c;
                    float v0 = stg[r * STG_LD + c];
                    float v1 = stg[r * STG_LD + c + 1];
                    float e0 = (j0     <= gi) ? __expf(v0) : 0.0f;
                    float e1 = (j0 + 1 <= gi) ? __expf(v1) : 0.0f;
                    __half2 h = __floats2half2_rn(e0, e1);
                    s += __low2float(h) + __high2float(h);
                    *(__half2*)&Cp[(size_t)gi * ldc + j0] = h;
                }
                #pragma unroll
                for (int o = 16; o; o >>= 1)
                    s += __shfl_xor_sync(0xFFFFFFFFu, s, o);
                if (lane == 0)
                    aux[(bz * T_ + gi) * NBLK + blockIdx.x] = s;
            } else {  // EPI == 3: row scale
                float sc = aux[bz * T_ + gi];
                #pragma unroll
                for (int cb = 0; cb < 2; cb++) {
                    const int c = cb * 64 + lane * 2;
                    float v0 = stg[r * STG_LD + c] * sc;
                    float v1 = stg[r * STG_LD + c + 1] * sc;
                    *(__half2*)&Cp[(size_t)gi * ldc + n0 + c] =
                        __floats2half2_rn(v0, v1);
                }
            }
        }
    }
}

// ---------------------------------------------------------------------------
// Launch
// ---------------------------------------------------------------------------
extern "C" void kernel_launch(void* const* d_in, const int* in_sizes, int n_in,
                              void* d_out, int out_size)
{
    const float* x     = (const float*)d_in[0];   // [B, T, C]
    const float* Wqkv  = (const float*)d_in[1];   // [C, 3C]
    const float* Wproj = (const float*)d_in[2];   // [C, C]
    float* out = (float*)d_out;                   // [B, T, C]

    static __half *xh = nullptr, *wqh = nullptr, *wph = nullptr;
    static __half *qkv = nullptr, *S = nullptr, *O = nullptr;
    static float *part = nullptr, *inv = nullptr;
    if (!qkv) {
        cudaGetSymbolAddress((void**)&xh,   g_xh);
        cudaGetSymbolAddress((void**)&wqh,  g_wqh);
        cudaGetSymbolAddress((void**)&wph,  g_wph);
        cudaGetSymbolAddress((void**)&qkv,  g_qkv);
        cudaGetSymbolAddress((void**)&S,    g_S);
        cudaGetSymbolAddress((void**)&O,    g_O);
        cudaGetSymbolAddress((void**)&part, g_part);
        cudaGetSymbolAddress((void**)&inv,  g_inv);
        cudaFuncSetAttribute(gemm_fp16_kernel<false, 0, 1>,
            cudaFuncAttributeMaxDynamicSharedMemorySize, (int)SMEM_BYTES);
        cudaFuncSetAttribute(gemm_fp16_kernel<true, 1, 2>,
            cudaFuncAttributeMaxDynamicSharedMemorySize, (int)SMEM_BYTES);
        cudaFuncSetAttribute(gemm_fp16_kernel<false, 2, 3>,
            cudaFuncAttributeMaxDynamicSharedMemorySize, (int)SMEM_BYTES);
        cudaFuncSetAttribute(gemm_fp16_kernel<false, 0, 0>,
            cudaFuncAttributeMaxDynamicSharedMemorySize, (int)SMEM_BYTES);
    }

    const float scale = 1.0f / 32.0f;   // C^-0.5
    dim3 blk(128);

    // 0. convert inputs to fp16
    f2h_kernel<<<(M_ROWS * C_ / 8 + 255) / 256, 256>>>(x, xh, M_ROWS * C_ / 8);
    f2h_kernel<<<(C_ * N_QKV / 8 + 255) / 256, 256>>>(Wqkv, wqh, C_ * N_QKV / 8);
    f2h_kernel<<<(C_ * C_ / 8 + 255) / 256, 256>>>(Wproj, wph, C_ * C_ / 8);

    // 1. qkv = x @ Wqkv (fp16 out, direct fragment store)
    gemm_fp16_kernel<false, 0, 1>
        <<<dim3(N_QKV / BN, M_ROWS / BM, 1), blk, SMEM_BYTES>>>(
        xh, wqh, qkv, nullptr, C_, C_, N_QKV, N_QKV, 0, 0, 0, 1.0f);

    // 2. E_b = exp(scale * Q_b @ K_b^T) causal-masked; partial row sums.
    gemm_fp16_kernel<true, 1, 2>
        <<<dim3(T_ / BN, T_ / BM, B_), blk, SMEM_BYTES>>>(
        qkv, qkv + C_, S, part, C_, N_QKV, N_QKV, T_,
        (long long)T_ * N_QKV, (long long)T_ * N_QKV, (long long)T_ * T_,
        scale);

    // 3. inv[row] = 1 / rowsum
    inv_rowsum_kernel<<<(M_ROWS + 255) / 256, 256>>>(part, inv);

    // 4. O_b = diag(inv) * E_b @ V_b (K-limited; fp16 out)
    gemm_fp16_kernel<false, 2, 3>
        <<<dim3(C_ / BN, T_ / BM, B_), blk, SMEM_BYTES>>>(
        S, qkv + 2 * C_, O, inv, T_, T_, N_QKV, C_,
        (long long)T_ * T_, (long long)T_ * N_QKV, (long long)T_ * C_,
        1.0f);

    // 5. out = O @ Wproj (fp32 final)
    gemm_fp16_kernel<false, 0, 0>
        <<<dim3(C_ / BN, M_ROWS / BM, 1), blk, SMEM_BYTES>>>(
        O, wph, out, nullptr, C_, C_, C_, C_, 0, 0, 0, 1.0f);
}

// round 16
// speedup vs baseline: 1.3907x; 1.0018x over previous
#include <cuda_runtime.h>
#include <cuda_fp16.h>
#include <mma.h>
#include <math.h>

using namespace nvcuda;

// Problem constants
constexpr int B_ = 8;
constexpr int T_ = 2048;
constexpr int C_ = 1024;
constexpr int M_ROWS = B_ * T_;      // 16384
constexpr int N_QKV  = 3 * C_;       // 3072
constexpr int NBLK   = T_ / 128;     // 16 col-blocks per row for partial sums

// GEMM tiling: 128x128 CTA tile, 4 warps (2Mx2N), warp tile 64x64, BK=32
constexpr int BM = 128;
constexpr int BN = 128;
constexpr int BK = 32;               // 32 halves = 64B per row
constexpr int AS_STRIDE = BK + 16;   // 48 halves
constexpr int BN_STRIDE = BN + 8;    // 136 halves
constexpr int A_BUF = BM * AS_STRIDE;   // 6144 halves (12KB)
constexpr int B_BUF = BM * AS_STRIDE;   // 6144 (>= 32*136=4352)
constexpr size_t SMEM_BYTES = 73728;    // GEMM (48KB) + epi staging (66KB)
constexpr int STG_LD = BN + 4;          // 132 floats, epi staging stride

// Scratch (device globals)
__device__ __half g_xh[(size_t)M_ROWS * C_];
__device__ __half g_wqh[(size_t)C_ * N_QKV];
__device__ __half g_wph[(size_t)C_ * C_];
__device__ __half g_qkv[(size_t)M_ROWS * N_QKV];   // [B*T, 3C]
__device__ __half g_S[(size_t)B_ * T_ * T_];       // E = exp(scores)
__device__ __half g_O[(size_t)M_ROWS * C_];
__device__ float  g_part[(size_t)M_ROWS * NBLK];
__device__ float  g_inv[(size_t)M_ROWS];

__device__ __forceinline__ unsigned smem_u32(const void* p) {
    return (unsigned)__cvta_generic_to_shared(p);
}
__device__ __forceinline__ void cp16(unsigned s, const void* g) {
    asm volatile("cp.async.cg.shared.global [%0], [%1], 16;\n" :: "r"(s), "l"(g));
}
__device__ __forceinline__ void cp_commit() {
    asm volatile("cp.async.commit_group;\n" ::: "memory");
}
template <int N>
__device__ __forceinline__ void cp_wait() {
    asm volatile("cp.async.wait_group %0;\n" :: "n"(N) : "memory");
}

// ---------------------------------------------------------------------------
// fp32 -> fp16 conversion, 8 elements per thread (16B stores)
// ---------------------------------------------------------------------------
__global__ void __launch_bounds__(256)
f2h_kernel(const float* __restrict__ in, __half* __restrict__ out, int n8)
{
    int i = blockIdx.x * blockDim.x + threadIdx.x;
    if (i >= n8) return;
    float4 a = ((const float4*)in)[2 * i];
    float4 b = ((const float4*)in)[2 * i + 1];
    __half2 h0 = __floats2half2_rn(a.x, a.y);
    __half2 h1 = __floats2half2_rn(a.z, a.w);
    __half2 h2 = __floats2half2_rn(b.x, b.y);
    __half2 h3 = __floats2half2_rn(b.z, b.w);
    uint4 u;
    u.x = *reinterpret_cast<unsigned*>(&h0);
    u.y = *reinterpret_cast<unsigned*>(&h1);
    u.z = *reinterpret_cast<unsigned*>(&h2);
    u.w = *reinterpret_cast<unsigned*>(&h3);
    ((uint4*)out)[i] = u;
}

// Deterministic row-sum inversion: inv[g] = 1 / sum_{bx<=i/128} part[g][bx]
__global__ void __launch_bounds__(256)
inv_rowsum_kernel(const float* __restrict__ part, float* __restrict__ inv)
{
    int g = blockIdx.x * blockDim.x + threadIdx.x;
    if (g >= M_ROWS) return;
    int i = g % T_;
    int nb = (i >> 7) + 1;
    float s = 0.0f;
    for (int b = 0; b < nb; b++) s += part[(size_t)g * NBLK + b];
    inv[g] = 1.0f / s;
}

// ---------------------------------------------------------------------------
// fp16 WMMA GEMM (fp32 accum), 128x128x32 tile, 128 threads (4 warps,
// warp tile 64x64, m16n16k16), cp.async double-buffered staging.
// (R10 core, verbatim — do not touch the main loop.)
// TRANS_B: B is [N,K] (A@B^T) else [K,N] (A@B).
// CAUSAL: 0 none; 1 skip blocks above diagonal; 2 K-limit to m0+BM.
// EPI: 0 fp32 store (final); 1 fp16 store DIRECT from fragments;
//      2 exp+mask+rowsum-partials (fp16); 3 row-scale by aux[row] (fp16).
// ---------------------------------------------------------------------------
template <bool TRANS_B, int CAUSAL, int EPI>
__global__ void __launch_bounds__(128, 2)
gemm_fp16_kernel(const __half* __restrict__ Ag, const __half* __restrict__ Bg,
                 void* __restrict__ Cgv, float* __restrict__ aux,
                 int K, int lda, int ldb, int ldc,
                 long long sA, long long sB, long long sC, float alpha)
{
    extern __shared__ char smem_raw[];
    __half* As = (__half*)smem_raw;                // [2][A_BUF]
    __half* Bs = (__half*)smem_raw + 2 * A_BUF;    // [2][B_BUF]

    const long long bz = blockIdx.z;
    const __half* A  = Ag + bz * sA;
    const __half* Bp = Bg + bz * sB;

    const int m0 = blockIdx.y * BM;
    const int n0 = blockIdx.x * BN;

    if (CAUSAL == 1 && n0 > m0 + BM - 1) return;
    int kend = K;
    if (CAUSAL == 2) kend = min(K, m0 + BM);
    const int ntiles = kend / BK;

    const int tid  = threadIdx.x;
    const int warp = tid >> 5;
    const int lane = tid & 31;
    const int wm   = (warp >> 1) * 64;
    const int wn   = (warp & 1) * 64;

    wmma::fragment<wmma::accumulator, 16, 16, 16, float> acc[4][4];
    #pragma unroll
    for (int i = 0; i < 4; i++)
        #pragma unroll
        for (int j = 0; j < 4; j++)
            wmma::fill_fragment(acc[i][j], 0.0f);

    auto stage = [&](int kt, int b) {
        const int kbase = kt * BK;
        // A tile 128x32 halves: 512 16B-chunks (8 halves each), 4/thread
        #pragma unroll
        for (int i = tid; i < (BM * BK) / 8; i += 128) {
            int r = i >> 2, c = (i & 3) * 8;
            cp16(smem_u32(&As[b * A_BUF + r * AS_STRIDE + c]),
                 &A[(size_t)(m0 + r) * lda + kbase + c]);
        }
        if constexpr (TRANS_B) {
            #pragma unroll
            for (int i = tid; i < (BN * BK) / 8; i += 128) {
                int r = i >> 2, c = (i & 3) * 8;
                cp16(smem_u32(&Bs[b * B_BUF + r * AS_STRIDE + c]),
                     &Bp[(size_t)(n0 + r) * ldb + kbase + c]);
            }
        } else {
            // B tile 32x128 halves: 512 chunks
            #pragma unroll
            for (int i = tid; i < (BK * BN) / 8; i += 128) {
                int r = i >> 4, c = (i & 15) * 8;
                cp16(smem_u32(&Bs[b * B_BUF + r * BN_STRIDE + c]),
                     &Bp[(size_t)(kbase + r) * ldb + n0 + c]);
            }
        }
    };

    stage(0, 0);
    cp_commit();

    using FragA = wmma::fragment<wmma::matrix_a, 16, 16, 16, __half,
                                 wmma::row_major>;

    for (int kt = 0; kt < ntiles; kt++) {
        const int buf = kt & 1;
        if (kt + 1 < ntiles) {
            stage(kt + 1, (kt + 1) & 1);
            cp_commit();
            cp_wait<1>();
        } else {
            cp_wait<0>();
        }
        __syncthreads();

        const __half* Abase = &As[buf * A_BUF];
        const __half* Bbase = &Bs[buf * B_BUF];

        #pragma unroll
        for (int kk = 0; kk < BK; kk += 16) {
            FragA af[4];
            #pragma unroll
            for (int im = 0; im < 4; im++)
                wmma::load_matrix_sync(af[im],
                    &Abase[(wm + im * 16) * AS_STRIDE + kk], AS_STRIDE);
            if constexpr (TRANS_B) {
                wmma::fragment<wmma::matrix_b, 16, 16, 16, __half,
                               wmma::col_major> bf[4];
                #pragma unroll
                for (int in = 0; in < 4; in++)
                    wmma::load_matrix_sync(bf[in],
                        &Bbase[(wn + in * 16) * AS_STRIDE + kk], AS_STRIDE);
                #pragma unroll
                for (int im = 0; im < 4; im++)
                    #pragma unroll
                    for (int in = 0; in < 4; in++)
                        wmma::mma_sync(acc[im][in], af[im], bf[in], acc[im][in]);
            } else {
                wmma::fragment<wmma::matrix_b, 16, 16, 16, __half,
                               wmma::row_major> bf[4];
                #pragma unroll
                for (int in = 0; in < 4; in++)
                    wmma::load_matrix_sync(bf[in],
                        &Bbase[kk * BN_STRIDE + wn + in * 16], BN_STRIDE);
                #pragma unroll
                for (int im = 0; im < 4; im++)
                    #pragma unroll
                    for (int in = 0; in < 4; in++)
                        wmma::mma_sync(acc[im][in], af[im], bf[in], acc[im][in]);
            }
        }
        __syncthreads();
    }

    // ---- alpha scale ----
    #pragma unroll
    for (int im = 0; im < 4; im++)
        #pragma unroll
        for (int in = 0; in < 4; in++)
            #pragma unroll
            for (int t = 0; t < acc[im][in].num_elements; t++)
                acc[im][in].x[t] *= alpha;

    if constexpr (EPI == 0) {
        float* Cp = (float*)Cgv + bz * sC;
        #pragma unroll
        for (int im = 0; im < 4; im++)
            #pragma unroll
            for (int in = 0; in < 4; in++)
                wmma::store_matrix_sync(
                    &Cp[(size_t)(m0 + wm + im * 16) * ldc + n0 + wn + in * 16],
                    acc[im][in], ldc, wmma::mem_row_major);
    } else if constexpr (EPI == 1) {
        // Direct fragment->fp16 conversion and store (no smem staging).
        // Element-wise copy between same-shape accumulator fragments is the
        // sanctioned idiom (cudaTensorCoreGemm sample).
        __half* Cp = (__half*)Cgv + bz * sC;
        #pragma unroll
        for (int im = 0; im < 4; im++)
            #pragma unroll
            for (int in = 0; in < 4; in++) {
                wmma::fragment<wmma::accumulator, 16, 16, 16, __half> hacc;
                #pragma unroll
                for (int t = 0; t < hacc.num_elements; t++)
                    hacc.x[t] = __float2half(acc[im][in].x[t]);
                wmma::store_matrix_sync(
                    &Cp[(size_t)(m0 + wm + im * 16) * ldc + n0 + wn + in * 16],
                    hacc, ldc, wmma::mem_row_major);
            }
    } else {
        __half* Cp = (__half*)Cgv + bz * sC;
        // Stage full 128x128 fp32 tile in smem, then half2 sweep.
        float* stg = (float*)smem_raw;   // 128 x 132 floats = 67584 B
        #pragma unroll
        for (int im = 0; im < 4; im++)
            #pragma unroll
            for (int in = 0; in < 4; in++)
                wmma::store_matrix_sync(
                    &stg[(wm + im * 16) * STG_LD + wn + in * 16],
                    acc[im][in], STG_LD, wmma::mem_row_major);
        __syncthreads();

        const int r0 = warp * 32;
        #pragma unroll 2
        for (int rr = 0; rr < 32; rr++) {
            const int r  = r0 + rr;
            const int gi = m0 + r;              // in-batch row (m0 < T)
            if constexpr (EPI == 2) {
                float s = 0.0f;
                #pragma unroll
                for (int cb = 0; cb < 2; cb++) {
                    const int c  = cb * 64 + lane * 2;
                    const int j0 = n0 + c;
                    float v0 = stg[r * STG_LD + c];
                    float v1 = stg[r * STG_LD + c + 1];
                    float e0 = (j0     <= gi) ? __expf(v0) : 0.0f;
                    float e1 = (j0 + 1 <= gi) ? __expf(v1) : 0.0f;
                    __half2 h = __floats2half2_rn(e0, e1);
                    s += __low2float(h) + __high2float(h);
                    *(__half2*)&Cp[(size_t)gi * ldc + j0] = h;
                }
                #pragma unroll
                for (int o = 16; o; o >>= 1)
                    s += __shfl_xor_sync(0xFFFFFFFFu, s, o);
                if (lane == 0)
                    aux[(bz * T_ + gi) * NBLK + blockIdx.x] = s;
            } else {  // EPI == 3: row scale
                float sc = aux[bz * T_ + gi];
                #pragma unroll
                for (int cb = 0; cb < 2; cb++) {
                    const int c = cb * 64 + lane * 2;
                    float v0 = stg[r * STG_LD + c] * sc;
                    float v1 = stg[r * STG_LD + c + 1] * sc;
                    *(__half2*)&Cp[(size_t)gi * ldc + n0 + c] =
                        __floats2half2_rn(v0, v1);
                }
            }
        }
    }
}

// ---------------------------------------------------------------------------
// Launch
// ---------------------------------------------------------------------------
extern "C" void kernel_launch(void* const* d_in, const int* in_sizes, int n_in,
                              void* d_out, int out_size)
{
    const float* x     = (const float*)d_in[0];   // [B, T, C]
    const float* Wqkv  = (const float*)d_in[1];   // [C, 3C]
    const float* Wproj = (const float*)d_in[2];   // [C, C]
    float* out = (float*)d_out;                   // [B, T, C]

    static __half *xh = nullptr, *wqh = nullptr, *wph = nullptr;
    static __half *qkv = nullptr, *S = nullptr, *O = nullptr;
    static float *part = nullptr, *inv = nullptr;
    if (!qkv) {
        cudaGetSymbolAddress((void**)&xh,   g_xh);
        cudaGetSymbolAddress((void**)&wqh,  g_wqh);
        cudaGetSymbolAddress((void**)&wph,  g_wph);
        cudaGetSymbolAddress((void**)&qkv,  g_qkv);
        cudaGetSymbolAddress((void**)&S,    g_S);
        cudaGetSymbolAddress((void**)&O,    g_O);
        cudaGetSymbolAddress((void**)&part, g_part);
        cudaGetSymbolAddress((void**)&inv,  g_inv);
        cudaFuncSetAttribute(gemm_fp16_kernel<false, 0, 1>,
            cudaFuncAttributeMaxDynamicSharedMemorySize, (int)SMEM_BYTES);
        cudaFuncSetAttribute(gemm_fp16_kernel<true, 1, 2>,
            cudaFuncAttributeMaxDynamicSharedMemorySize, (int)SMEM_BYTES);
        cudaFuncSetAttribute(gemm_fp16_kernel<false, 2, 3>,
            cudaFuncAttributeMaxDynamicSharedMemorySize, (int)SMEM_BYTES);
        cudaFuncSetAttribute(gemm_fp16_kernel<false, 0, 0>,
            cudaFuncAttributeMaxDynamicSharedMemorySize, (int)SMEM_BYTES);
    }

    const float scale = 1.0f / 32.0f;   // C^-0.5
    dim3 blk(128);

    // 0. convert inputs to fp16
    f2h_kernel<<<(M_ROWS * C_ / 8 + 255) / 256, 256>>>(x, xh, M_ROWS * C_ / 8);
    f2h_kernel<<<(C_ * N_QKV / 8 + 255) / 256, 256>>>(Wqkv, wqh, C_ * N_QKV / 8);
    f2h_kernel<<<(C_ * C_ / 8 + 255) / 256, 256>>>(Wproj, wph, C_ * C_ / 8);

    // 1. qkv = x @ Wqkv (fp16 out, direct fragment store)
    gemm_fp16_kernel<false, 0, 1>
        <<<dim3(N_QKV / BN, M_ROWS / BM, 1), blk, SMEM_BYTES>>>(
        xh, wqh, qkv, nullptr, C_, C_, N_QKV, N_QKV, 0, 0, 0, 1.0f);

    // 2. E_b = exp(scale * Q_b @ K_b^T) causal-masked; partial row sums.
    gemm_fp16_kernel<true, 1, 2>
        <<<dim3(T_ / BN, T_ / BM, B_), blk, SMEM_BYTES>>>(
        qkv, qkv + C_, S, part, C_, N_QKV, N_QKV, T_,
        (long long)T_ * N_QKV, (long long)T_ * N_QKV, (long long)T_ * T_,
        scale);

    // 3. inv[row] = 1 / rowsum
    inv_rowsum_kernel<<<(M_ROWS + 255) / 256, 256>>>(part, inv);

    // 4. O_b = diag(inv) * E_b @ V_b (K-limited; fp16 out)
    gemm_fp16_kernel<false, 2, 3>
        <<<dim3(C_ / BN, T_ / BM, B_), blk, SMEM_BYTES>>>(
        S, qkv + 2 * C_, O, inv, T_, T_, N_QKV, C_,
        (long long)T_ * T_, (long long)T_ * N_QKV, (long long)T_ * C_,
        1.0f);

    // 5. out = O @ Wproj (fp32 final)
    gemm_fp16_kernel<false, 0, 0>
        <<<dim3(C_ / BN, M_ROWS / BM, 1), blk, SMEM_BYTES>>>(
        O, wph, out, nullptr, C_, C_, C_, C_, 0, 0, 0, 1.0f);
}